// round 6
// baseline (speedup 1.0000x reference)
#include <cuda_runtime.h>
#include <cuda_bf16.h>

#define HIMG 240
#define WIMG 135
#define HW   (HIMG * WIMG)
#define NF   1000
#define NV   600
#define INV_SIGMA 1.0e4f
#define BLURF 9.210240366975849e-4f
#define BAND  0.05f

#define NB   148                 // one block per SM -> co-residency guaranteed
#define NT   512                 // 16 warps
#define NWARPS (NB * (NT / 32))  // 2368
#define CH   4                   // rows per work item
#define MAXITEMS (NF * ((HIMG + CH - 1) / CH))

struct __align__(16) FD {
    float ax, ay, bx, by, cx, cy;
    float e0x, e0y, e1x, e1y, e2x, e2y;
    float rl0, rl1, rl2, rd0, rd1, rd2;
    int x0, x1, y0, y1;
};

__device__ FD       g_face[NF];
__device__ unsigned g_items[MAXITEMS];
__device__ unsigned g_total   = 0;  // item count; reset in phase 3 each launch
__device__ float    g_sum[HW];      // zeroed in phase 0 each launch
__device__ float    g_flag[HW];     // zeroed in phase 0 each launch
__device__ unsigned g_count   = 0;  // barrier arrivals; self-resets
__device__ unsigned g_release = 0;  // monotonic across graph replays

__device__ __forceinline__ void grid_barrier(unsigned base, unsigned r) {
    __syncthreads();
    if (threadIdx.x == 0) {
        __threadfence();
        unsigned old = atomicAdd(&g_count, 1);
        if (old == NB - 1) {
            g_count = 0;
            __threadfence();
            atomicAdd(&g_release, 1);
        } else {
            while (atomicAdd(&g_release, 0) - base < r) { }
        }
        __threadfence();
    }
    __syncthreads();
}

__global__ void __launch_bounds__(NT, 1)
silhouette_fused(const float* __restrict__ verts,
                 const int*   __restrict__ faces,
                 const float* __restrict__ gt,
                 float* __restrict__ out /* [0]=loss, [1..]=sil */) {
    __shared__ unsigned s_base;
    __shared__ float    ws[16];

    const int tid  = threadIdx.x;
    const int lane = tid & 31;
    const int warp = tid >> 5;
    const int bid  = blockIdx.x;
    const int gtid = bid * NT + tid;

    if (tid == 0) s_base = atomicAdd(&g_release, 0u);

    // ---------------- Phase 0: zero accumulators; face setup + item push ---
    if (gtid < HW) { g_sum[gtid] = 0.0f; g_flag[gtid] = 0.0f; }
    if (gtid == 0) out[0] = 0.0f;

    if (gtid < NF) {
        const int f = gtid;
        int idx[3];
        idx[0] = faces[3 * f + 0];
        idx[1] = faces[3 * f + 1];
        idx[2] = faces[3 * f + 2];

        float Px[3], Py[3], zs[3];
#pragma unroll
        for (int k = 0; k < 3; k++) {
            float x = verts[3 * idx[k] + 0];
            float y = verts[3 * idx[k] + 1];
            float z = verts[3 * idx[k] + 2];
            float vx = -x, vy = -y, vz = z;      // R = diag(-1,-1,1)
            zs[k] = vz;
            float zz = fmaxf(vz, 1e-6f);
            Px[k] = (__fdividef(1000.0f * vx, zz) + 512.0f) * ((float)WIMG / 1024.0f);
            Py[k] = (__fdividef(1000.0f * vy, zz) + 512.0f) * ((float)HIMG / 1024.0f);
        }
        float tz = (zs[0] + zs[1] + zs[2]) * (1.0f / 3.0f);

        FD fd;
        fd.ax = Px[0]; fd.ay = Py[0];
        fd.bx = Px[1]; fd.by = Py[1];
        fd.cx = Px[2]; fd.cy = Py[2];
        fd.e0x = fd.bx - fd.ax; fd.e0y = fd.by - fd.ay;
        fd.e1x = fd.cx - fd.bx; fd.e1y = fd.cy - fd.by;
        fd.e2x = fd.ax - fd.cx; fd.e2y = fd.ay - fd.cy;
        float l0 = fd.e0x * fd.e0x + fd.e0y * fd.e0y + 1e-12f;
        float l1 = fd.e1x * fd.e1x + fd.e1y * fd.e1y + 1e-12f;
        float l2 = fd.e2x * fd.e2x + fd.e2y * fd.e2y + 1e-12f;
        fd.rl0 = rsqrtf(l0); fd.rl1 = rsqrtf(l1); fd.rl2 = rsqrtf(l2);
        fd.rd0 = fd.rl0 * fd.rl0;
        fd.rd1 = fd.rl1 * fd.rl1;
        fd.rd2 = fd.rl2 * fd.rl2;

        bool skip = !(tz > 1e-6f);
        if (!skip) {
            float minx = fminf(fd.ax, fminf(fd.bx, fd.cx));
            float maxx = fmaxf(fd.ax, fmaxf(fd.bx, fd.cx));
            float miny = fminf(fd.ay, fminf(fd.by, fd.cy));
            float maxy = fmaxf(fd.ay, fmaxf(fd.by, fd.cy));
            fd.x0 = max(0, (int)floorf(minx) - 1);
            fd.x1 = min(WIMG - 1, (int)ceilf(maxx));
            fd.y0 = max(0, (int)floorf(miny) - 1);
            fd.y1 = min(HIMG - 1, (int)ceilf(maxy));
            // point-degenerate: reference marks every pixel inside
            if (fd.e0x == 0.0f && fd.e0y == 0.0f &&
                fd.e1x == 0.0f && fd.e1y == 0.0f) {
                fd.x0 = 0; fd.x1 = WIMG - 1; fd.y0 = 0; fd.y1 = HIMG - 1;
            }
        } else {
            fd.x0 = 1; fd.x1 = 0; fd.y0 = 1; fd.y1 = 0;
        }
        g_face[f] = fd;

        if (!skip) {
            int h = fd.y1 - fd.y0 + 1;
            int n = (h + CH - 1) / CH;
            if (n > 0) {
                unsigned basei = atomicAdd(&g_total, (unsigned)n);
                for (int j = 0; j < n; j++)
                    g_items[basei + j] =
                        (unsigned)f | ((unsigned)(fd.y0 + j * CH) << 16);
            }
        }
    }
    __syncthreads();
    const unsigned base = s_base;

    grid_barrier(base, 1);

    // ---------------- Phase 1: warps consume row-chunk items ---------------
    {
        unsigned total = atomicAdd(&g_total, 0u);   // post-barrier read
        int gw = (bid * NT + tid) >> 5;
        for (unsigned it = (unsigned)gw; it < total; it += NWARPS) {
            unsigned item = g_items[it];
            int f  = (int)(item & 0xFFFFu);
            int ys = (int)(item >> 16);
            const FD fd = g_face[f];                 // uniform -> broadcast
            int ye = min(ys + CH - 1, fd.y1);

            for (int iy = ys; iy <= ye; iy++) {
                float py  = (float)iy + 0.5f;
                int   row = iy * WIMG;
                for (int ix = fd.x0 + lane; ix <= fd.x1; ix += 32) {
                    float px = (float)ix + 0.5f;

                    float apx0 = px - fd.ax, apy0 = py - fd.ay;
                    float apx1 = px - fd.bx, apy1 = py - fd.by;
                    float apx2 = px - fd.cx, apy2 = py - fd.cy;

                    float c0 = fd.e0x * apy0 - fd.e0y * apx0;
                    float c1 = fd.e1x * apy1 - fd.e1y * apx1;
                    float c2 = fd.e2x * apy2 - fd.e2y * apx2;
                    bool inside = (c0 >= 0.0f && c1 >= 0.0f && c2 >= 0.0f) ||
                                  (c0 <= 0.0f && c1 <= 0.0f && c2 <= 0.0f);

                    float dl = fminf(fabsf(c0) * fd.rl0,
                               fminf(fabsf(c1) * fd.rl1, fabsf(c2) * fd.rl2));

                    if (inside && dl > BAND) {
                        // log contribution <= -25: alpha saturates -> flag
                        g_flag[row + ix] = 1.0f;       // idempotent store
                    } else if (inside || dl <= BAND) {
                        float t0 = fminf(fmaxf((apx0 * fd.e0x + apy0 * fd.e0y) * fd.rd0, 0.0f), 1.0f);
                        float rx = apx0 - t0 * fd.e0x;
                        float ry = apy0 - t0 * fd.e0y;
                        float d2min = rx * rx + ry * ry;

                        float t1 = fminf(fmaxf((apx1 * fd.e1x + apy1 * fd.e1y) * fd.rd1, 0.0f), 1.0f);
                        rx = apx1 - t1 * fd.e1x;
                        ry = apy1 - t1 * fd.e1y;
                        d2min = fminf(d2min, rx * rx + ry * ry);

                        float t2 = fminf(fmaxf((apx2 * fd.e2x + apy2 * fd.e2y) * fd.rd2, 0.0f), 1.0f);
                        rx = apx2 - t2 * fd.e2x;
                        ry = apy2 - t2 * fd.e2y;
                        d2min = fminf(d2min, rx * rx + ry * ry);

                        if (inside || d2min <= BLURF) {
                            float u = (inside ? d2min : -d2min) * INV_SIGMA;
                            // log1p(-sigmoid(u)) == -softplus(u)
                            float sp = (u > 15.0f) ? u : log1pf(__expf(u));
                            if (sp != 0.0f) atomicAdd(&g_sum[row + ix], -sp);
                        }
                    }
                    // outside & dl > BAND: d2 > BLURF -> reference-invalid
                }
            }
        }
    }

    grid_barrier(base, 2);

    // ---------------- Phase 2: finalize (1 px/thread) + loss reduce --------
    if (gtid == 0) g_total = 0;          // reset queue for next graph replay

    float local = 0.0f;
    if (gtid < HW) {
        float s  = g_sum[gtid];
        float fl = g_flag[gtid];
        float alpha = (fl != 0.0f) ? 1.0f : (1.0f - expf(s));
        out[1 + gtid] = alpha;
        local = fabsf(alpha - gt[gtid]);
    }
#pragma unroll
    for (int o = 16; o > 0; o >>= 1)
        local += __shfl_down_sync(0xffffffffu, local, o);
    if (lane == 0) ws[warp] = local;
    __syncthreads();
    if (warp == 0) {
        float v = (lane < (NT >> 5)) ? ws[lane] : 0.0f;
#pragma unroll
        for (int o = 8; o > 0; o >>= 1)
            v += __shfl_down_sync(0xffffu, v, o);
        if (lane == 0 && v != 0.0f)
            atomicAdd(out, v * (1.0f / (float)HW));
    }
}

extern "C" void kernel_launch(void* const* d_in, const int* in_sizes, int n_in,
                              void* d_out, int out_size) {
    const float* verts = nullptr;
    const float* gt    = nullptr;
    const int*   faces = nullptr;
    for (int i = 0; i < n_in; i++) {
        if (in_sizes[i] == NV * 3)      verts = (const float*)d_in[i];
        else if (in_sizes[i] == HW)     gt    = (const float*)d_in[i];
        else if (in_sizes[i] == NF * 3) faces = (const int*)d_in[i];
    }
    float* out = (float*)d_out;
    (void)out_size;
    silhouette_fused<<<NB, NT>>>(verts, faces, gt, out);
}

// round 7
// speedup vs baseline: 4.3433x; 4.3433x over previous
#include <cuda_runtime.h>
#include <cuda_bf16.h>

#define HIMG 240
#define WIMG 135
#define HW   (HIMG * WIMG)
#define NF   1000
#define NV   600
#define INV_SIGMA 1.0e4f
#define BLURF 9.210240366975849e-4f
#define BAND  0.05f

#define NT    256          // 8 warps
#define SPLIT 4            // row-slices per face

struct __align__(16) FD {
    float ax, ay, bx, by, cx, cy;
    float e0x, e0y, e1x, e1y, e2x, e2y;
    float rl0, rl1, rl2, rd0, rd1, rd2;
    int x0, x1, y0, y1;
    int skip;
};

__device__ float g_sum[HW];   // zero at module load; finalize self-cleans
__device__ float g_flag[HW];  // zero at module load; finalize self-cleans

// ---------------------------------------------------------------------------
// Raster: grid (NF, SPLIT). Block (f, sl) handles rows of face f whose
// bbox-relative index is congruent to sl mod SPLIT. Setup once per block
// (warp 0 -> smem broadcast).
// ---------------------------------------------------------------------------
__global__ void __launch_bounds__(NT)
raster_kernel(const float* __restrict__ verts,
              const int*   __restrict__ faces,
              float* __restrict__ out) {
    __shared__ FD sfd;

    const int tid  = threadIdx.x;
    const int lane = tid & 31;
    const int warp = tid >> 5;                  // 0..7
    const int f    = blockIdx.x;
    const int sl   = blockIdx.y;

    if (f == 0 && sl == 0 && tid == 0) out[0] = 0.0f;   // loss accumulator

    // ---- setup (warp 0 only; redundant across its lanes, loads broadcast) -
    if (warp == 0) {
        int idx[3];
        idx[0] = faces[3 * f + 0];
        idx[1] = faces[3 * f + 1];
        idx[2] = faces[3 * f + 2];

        float Px[3], Py[3], zs[3];
#pragma unroll
        for (int k = 0; k < 3; k++) {
            float x = verts[3 * idx[k] + 0];
            float y = verts[3 * idx[k] + 1];
            float z = verts[3 * idx[k] + 2];
            float vx = -x, vy = -y, vz = z;     // R = diag(-1,-1,1)
            zs[k] = vz;
            float zz = fmaxf(vz, 1e-6f);
            Px[k] = (__fdividef(1000.0f * vx, zz) + 512.0f) * ((float)WIMG / 1024.0f);
            Py[k] = (__fdividef(1000.0f * vy, zz) + 512.0f) * ((float)HIMG / 1024.0f);
        }
        float tz = (zs[0] + zs[1] + zs[2]) * (1.0f / 3.0f);

        FD fd;
        fd.ax = Px[0]; fd.ay = Py[0];
        fd.bx = Px[1]; fd.by = Py[1];
        fd.cx = Px[2]; fd.cy = Py[2];
        fd.e0x = fd.bx - fd.ax; fd.e0y = fd.by - fd.ay;
        fd.e1x = fd.cx - fd.bx; fd.e1y = fd.cy - fd.by;
        fd.e2x = fd.ax - fd.cx; fd.e2y = fd.ay - fd.cy;
        float l0 = fd.e0x * fd.e0x + fd.e0y * fd.e0y + 1e-12f;
        float l1 = fd.e1x * fd.e1x + fd.e1y * fd.e1y + 1e-12f;
        float l2 = fd.e2x * fd.e2x + fd.e2y * fd.e2y + 1e-12f;
        fd.rl0 = rsqrtf(l0); fd.rl1 = rsqrtf(l1); fd.rl2 = rsqrtf(l2);
        fd.rd0 = fd.rl0 * fd.rl0;
        fd.rd1 = fd.rl1 * fd.rl1;
        fd.rd2 = fd.rl2 * fd.rl2;

        fd.skip = !(tz > 1e-6f);
        if (!fd.skip) {
            float minx = fminf(fd.ax, fminf(fd.bx, fd.cx));
            float maxx = fmaxf(fd.ax, fmaxf(fd.bx, fd.cx));
            float miny = fminf(fd.ay, fminf(fd.by, fd.cy));
            float maxy = fmaxf(fd.ay, fmaxf(fd.by, fd.cy));
            fd.x0 = max(0, (int)floorf(minx) - 1);
            fd.x1 = min(WIMG - 1, (int)ceilf(maxx));
            fd.y0 = max(0, (int)floorf(miny) - 1);
            fd.y1 = min(HIMG - 1, (int)ceilf(maxy));
            // point-degenerate: reference marks every pixel inside
            if (fd.e0x == 0.0f && fd.e0y == 0.0f &&
                fd.e1x == 0.0f && fd.e1y == 0.0f) {
                fd.x0 = 0; fd.x1 = WIMG - 1; fd.y0 = 0; fd.y1 = HIMG - 1;
            }
        } else {
            fd.x0 = 1; fd.x1 = 0; fd.y0 = 1; fd.y1 = 0;
        }
        if (lane == 0) sfd = fd;
    }
    __syncthreads();
    const FD fd = sfd;
    if (fd.skip) return;

    // ---- sweep rows with (row - y0) % SPLIT == sl; warps stride by 8 ------
    const int nrows = fd.y1 - fd.y0 + 1;
    for (int r = sl + warp * SPLIT; r < nrows; r += 8 * SPLIT) {
        int   iy  = fd.y0 + r;
        float py  = (float)iy + 0.5f;
        int   row = iy * WIMG;
        for (int ix = fd.x0 + lane; ix <= fd.x1; ix += 32) {
            float px = (float)ix + 0.5f;

            float apx0 = px - fd.ax, apy0 = py - fd.ay;
            float apx1 = px - fd.bx, apy1 = py - fd.by;
            float apx2 = px - fd.cx, apy2 = py - fd.cy;

            float c0 = fd.e0x * apy0 - fd.e0y * apx0;
            float c1 = fd.e1x * apy1 - fd.e1y * apx1;
            float c2 = fd.e2x * apy2 - fd.e2y * apx2;
            bool inside = (c0 >= 0.0f && c1 >= 0.0f && c2 >= 0.0f) ||
                          (c0 <= 0.0f && c1 <= 0.0f && c2 <= 0.0f);

            // conservative perpendicular distance to nearest edge line
            float dl = fminf(fabsf(c0) * fd.rl0,
                       fminf(fabsf(c1) * fd.rl1, fabsf(c2) * fd.rl2));

            if (inside && dl > BAND) {
                // log contribution <= -25: alpha saturates -> idempotent flag
                g_flag[row + ix] = 1.0f;
            } else if (inside || dl <= BAND) {
                // exact reference math (segment distances)
                float t0 = fminf(fmaxf((apx0 * fd.e0x + apy0 * fd.e0y) * fd.rd0, 0.0f), 1.0f);
                float rx = apx0 - t0 * fd.e0x;
                float ry = apy0 - t0 * fd.e0y;
                float d2min = rx * rx + ry * ry;

                float t1 = fminf(fmaxf((apx1 * fd.e1x + apy1 * fd.e1y) * fd.rd1, 0.0f), 1.0f);
                rx = apx1 - t1 * fd.e1x;
                ry = apy1 - t1 * fd.e1y;
                d2min = fminf(d2min, rx * rx + ry * ry);

                float t2 = fminf(fmaxf((apx2 * fd.e2x + apy2 * fd.e2y) * fd.rd2, 0.0f), 1.0f);
                rx = apx2 - t2 * fd.e2x;
                ry = apy2 - t2 * fd.e2y;
                d2min = fminf(d2min, rx * rx + ry * ry);

                if (inside || d2min <= BLURF) {
                    float u = (inside ? d2min : -d2min) * INV_SIGMA;
                    // log1p(-sigmoid(u)) == -softplus(u)
                    float sp = (u > 15.0f) ? u : log1pf(__expf(u));
                    if (sp != 0.0f) atomicAdd(&g_sum[row + ix], -sp);
                }
            }
            // outside & dl > BAND: d2min >= dl^2 > BLURF -> reference-invalid
        }
    }
}

// ---------------------------------------------------------------------------
// Finalize: alpha, sil, loss; self-clean accumulators for next graph replay.
// ---------------------------------------------------------------------------
__global__ void __launch_bounds__(256)
finalize_kernel(const float* __restrict__ gt,
                float* __restrict__ out) {
    int i = blockIdx.x * blockDim.x + threadIdx.x;
    float local = 0.0f;
    if (i < HW) {
        float s  = g_sum[i];
        float fl = g_flag[i];
        g_sum[i]  = 0.0f;
        g_flag[i] = 0.0f;
        float alpha = (fl != 0.0f) ? 1.0f : (1.0f - expf(s));
        out[1 + i] = alpha;
        local = fabsf(alpha - gt[i]);
    }
#pragma unroll
    for (int o = 16; o > 0; o >>= 1)
        local += __shfl_down_sync(0xffffffffu, local, o);

    __shared__ float ws[8];
    int lane = threadIdx.x & 31;
    int wid  = threadIdx.x >> 5;
    if (lane == 0) ws[wid] = local;
    __syncthreads();
    if (wid == 0) {
        local = (lane < 8) ? ws[lane] : 0.0f;
#pragma unroll
        for (int o = 4; o > 0; o >>= 1)
            local += __shfl_down_sync(0xffu, local, o);
        if (lane == 0)
            atomicAdd(out, local * (1.0f / (float)HW));
    }
}

// ---------------------------------------------------------------------------
extern "C" void kernel_launch(void* const* d_in, const int* in_sizes, int n_in,
                              void* d_out, int out_size) {
    const float* verts = nullptr;
    const float* gt    = nullptr;
    const int*   faces = nullptr;
    for (int i = 0; i < n_in; i++) {
        if (in_sizes[i] == NV * 3)      verts = (const float*)d_in[i];
        else if (in_sizes[i] == HW)     gt    = (const float*)d_in[i];
        else if (in_sizes[i] == NF * 3) faces = (const int*)d_in[i];
    }
    float* out = (float*)d_out;
    (void)out_size;
    raster_kernel<<<dim3(NF, SPLIT), NT>>>(verts, faces, out);
    finalize_kernel<<<(HW + 255) / 256, 256>>>(gt, out);
}